// round 15
// baseline (speedup 1.0000x reference)
#include <cuda_runtime.h>
#include <math.h>

#define Bc 16
#define Lc 4096
#define Hc 256
#define DINc 257
#define DOUTc 257
#define NLc 4
#define BHLc (Bc*Hc*Lc)

__device__ float  g_xr[BHLc];
__device__ float  g_xi[BHLc];
__device__ float  g_conv[4*BHLc];
__device__ float  g_glu[4*BHLc];
__device__ float  g_encT[2][DINc*Hc];
__device__ float  g_decT[2][Hc*DOUTc];
__device__ float  g_woutT[8*131072];   // [lj][hp][h][{a,g}] pairs
__device__ float4 g_coef[NLc*2*Hc*32];

typedef unsigned long long u64;

__device__ __forceinline__ u64 pack2(float v){ u64 r; asm("mov.b64 %0, {%1, %1};" : "=l"(r) : "f"(v)); return r; }
__device__ __forceinline__ u64 pk(float a, float b){ u64 r; asm("mov.b64 %0, {%1, %2};" : "=l"(r) : "f"(a), "f"(b)); return r; }
__device__ __forceinline__ u64 fma2(u64 a, u64 b, u64 c){ u64 d; asm("fma.rn.f32x2 %0, %1, %2, %3;" : "=l"(d) : "l"(a), "l"(b), "l"(c)); return d; }
__device__ __forceinline__ u64 mul2(u64 a, u64 b){ u64 d; asm("mul.rn.f32x2 %0, %1, %2;" : "=l"(d) : "l"(a), "l"(b)); return d; }
__device__ __forceinline__ float2 upk(u64 v){ float2 r; asm("mov.b64 {%0, %1}, %2;" : "=f"(r.x), "=f"(r.y) : "l"(v)); return r; }

// ---------- setup: weight transposes + SSM coefficients ----------
__global__ void k_setup(const float* __restrict__ eWr, const float* __restrict__ eWi,
                        const float* __restrict__ dWr, const float* __restrict__ dWi,
                        const float* __restrict__ Wout,
                        const float* __restrict__ ldt, const float* __restrict__ lAr,
                        const float* __restrict__ Aim, const float* __restrict__ C2){
    int t0 = blockIdx.x*blockDim.x + threadIdx.x;
    int NT = gridDim.x*blockDim.x;
    for (int i = t0; i < DINc*Hc; i += NT){
        int d = i >> 8, h = i & 255;
        g_encT[0][i] = eWr[h*DINc + d];
        g_encT[1][i] = eWi[h*DINc + d];
    }
    for (int i = t0; i < Hc*DOUTc; i += NT){
        int h = i / DOUTc, o = i % DOUTc;
        g_decT[0][i] = dWr[o*Hc + h];
        g_decT[1][i] = dWi[o*Hc + h];
    }
    for (int i = t0; i < 8*131072; i += NT){
        int lj = i >> 17, r = i & 131071;
        int hp = r >> 9, h = (r >> 1) & 255, ag = r & 1;
        g_woutT[i] = Wout[lj*131072 + (ag*256 + h)*256 + hp];
    }
    for (int t = t0; t < NLc*2*Hc*32; t += NT){
        int h = (t >> 5) & 255, lj = t >> 13;
        double dt = exp((double)ldt[lj*256 + h]);
        double Ar = -exp((double)lAr[t]);
        double Ai = (double)Aim[t];
        double er = exp(dt*Ar);
        double wr = er*cos(dt*Ai), wi = er*sin(dt*Ai);
        double den = Ar*Ar + Ai*Ai;
        double Fr = ((wr-1.0)*Ar + wi*Ai)/den;
        double Fi = (wi*Ar - (wr-1.0)*Ai)/den;
        double Cr = (double)C2[t*2], Ci = (double)C2[t*2+1];
        g_coef[t] = make_float4((float)wr, (float)wi,
                                (float)(2.0*(Cr*Fr - Ci*Fi)), (float)(-2.0*(Cr*Fi + Ci*Fr)));
    }
}

// ---------- encoder ----------
__global__ __launch_bounds__(256) void k_encoder(const float* __restrict__ x,
                                                 const float* __restrict__ br, const float* __restrict__ bi){
    __shared__ __align__(16) float xsr[DINc*16];
    __shared__ __align__(16) float xsi[DINc*16];
    int b = blockIdx.x >> 8, l0 = (blockIdx.x & 255) << 4, tid = threadIdx.x;
    const float* xb = x + ((long long)(b*Lc + l0))*DINc*2;
    for (int i = tid; i < 16*DINc*2; i += 256){
        int t = i / (DINc*2), dd = i % (DINc*2);
        float v = xb[i];
        if (dd & 1) xsi[(dd>>1)*16 + t] = v; else xsr[(dd>>1)*16 + t] = v;
    }
    __syncthreads();
    int h = tid;
    u64 yr[8], yi[8];
    #pragma unroll
    for (int p = 0; p < 8; ++p){ yr[p] = 0ull; yi[p] = 0ull; }
    for (int d = 0; d < DINc; ++d){
        u64 wr2 = pack2(g_encT[0][d*256 + h]);
        float wif = g_encT[1][d*256 + h];
        u64 wi2 = pack2(wif), nwi2 = pack2(-wif);
        const ulonglong2* xr4 = (const ulonglong2*)&xsr[d*16];
        const ulonglong2* xi4 = (const ulonglong2*)&xsi[d*16];
        #pragma unroll
        for (int j = 0; j < 4; ++j){
            ulonglong2 xr = xr4[j], xi = xi4[j];
            yr[2*j]   = fma2(wr2, xr.x, yr[2*j]);   yr[2*j]   = fma2(nwi2, xi.x, yr[2*j]);
            yi[2*j]   = fma2(wi2, xr.x, yi[2*j]);   yi[2*j]   = fma2(wr2,  xi.x, yi[2*j]);
            yr[2*j+1] = fma2(wr2, xr.y, yr[2*j+1]); yr[2*j+1] = fma2(nwi2, xi.y, yr[2*j+1]);
            yi[2*j+1] = fma2(wi2, xr.y, yi[2*j+1]); yi[2*j+1] = fma2(wr2,  xi.y, yi[2*j+1]);
        }
    }
    float brv = br[h], biv = bi[h];
    float2* pr = (float2*)&g_xr[(b*Hc + h)*Lc + l0];
    float2* pi = (float2*)&g_xi[(b*Hc + h)*Lc + l0];
    #pragma unroll
    for (int p = 0; p < 8; ++p){
        float2 a = upk(yr[p]), c = upk(yi[p]);
        pr[p] = make_float2(a.x + brv, a.y + brv);
        pi[p] = make_float2(c.x + biv, c.y + biv);
    }
}

// ---------- scan: 4 threads/(b,h), u prefetch, dual reduction accumulators ----------
__global__ __launch_bounds__(128) void k_scan(int layer, const float* __restrict__ s4D){
    int e = blockIdx.x >> 7, bhb = blockIdx.x & 127, tid = threadIdx.x;
    int g = tid >> 2, q = tid & 3;
    int bh = bhb*32 + g, h = bh & 255, jb = e & 1;
    const float* u = ((e == 0 || e == 3) ? g_xr : g_xi) + bh*Lc;
    float* outp = g_conv + e*BHLc + bh*Lc;
    u64 wr2[4], wi2[4], nwi2[4], kr2[4], ki2[4], sr2[4], si2[4];
    int cbase = ((layer*2 + jb)*256 + h)*32 + q*8;
    #pragma unroll
    for (int m = 0; m < 4; ++m){
        float4 c0 = g_coef[cbase + 2*m];
        float4 c1 = g_coef[cbase + 2*m + 1];
        wr2[m] = pk(c0.x, c1.x); wi2[m] = pk(c0.y, c1.y); nwi2[m] = pk(-c0.y, -c1.y);
        kr2[m] = pk(c0.z, c1.z); ki2[m] = pk(c0.w, c1.w);
        sr2[m] = 0ull; si2[m] = 0ull;
    }
    float Dv = s4D[(layer*2 + jb)*256 + h];
    float4 uv = *(const float4*)(u);
    for (int l = 0; l < Lc; l += 4){
        float4 uvn = (l + 4 < Lc) ? *(const float4*)(u + l + 4) : uv;
        float us[4] = {uv.x, uv.y, uv.z, uv.w};
        float cc[4];
        #pragma unroll
        for (int s = 0; s < 4; ++s){
            u64 u2 = pack2(us[s]), c2a = 0ull, c2b = 0ull;
            #pragma unroll
            for (int m = 0; m < 4; ++m){
                u64 t0 = fma2(wr2[m], sr2[m], u2);
                t0 = fma2(nwi2[m], si2[m], t0);
                u64 t1 = mul2(wr2[m], si2[m]);
                t1 = fma2(wi2[m], sr2[m], t1);
                sr2[m] = t0; si2[m] = t1;
                if (m & 1){ c2b = fma2(kr2[m], t0, c2b); c2b = fma2(ki2[m], t1, c2b); }
                else      { c2a = fma2(kr2[m], t0, c2a); c2a = fma2(ki2[m], t1, c2a); }
            }
            float2 ca = upk(c2a), cb = upk(c2b);
            float c = (ca.x + ca.y) + (cb.x + cb.y);
            c += __shfl_xor_sync(0xffffffffu, c, 1);
            c += __shfl_xor_sync(0xffffffffu, c, 2);
            cc[s] = fmaf(Dv, us[s], c);
        }
        if (q == 0){
            float4 gv;
            gv.x = 0.5f*cc[0]*(1.0f + erff(cc[0]*0.70710678f));
            gv.y = 0.5f*cc[1]*(1.0f + erff(cc[1]*0.70710678f));
            gv.z = 0.5f*cc[2]*(1.0f + erff(cc[2]*0.70710678f));
            gv.w = 0.5f*cc[3]*(1.0f + erff(cc[3]*0.70710678f));
            *(float4*)(outp + l) = gv;
        }
        uv = uvn;
    }
}

// ---------- FFMA2 GEMM + GLU: 64 threads, 8 weight rows (4 h x a/g), 16-ts tiles ----------
// Per hp: 64 fma2 + 4 LDS.128 + 4 LDG.64 + ~4 misc -> fma issue fraction ~84%.
__global__ void __launch_bounds__(64) k_gemm(int layer, const float* __restrict__ bout){
    __shared__ __align__(16) float ygs[256*16];      // 16 KB
    int tid = threadIdx.x;
    int e = blockIdx.x >> 12, b = (blockIdx.x >> 8) & 15, l0 = (blockIdx.x & 255) << 4;
    int lj = layer*2 + (e & 1);
    const float* src = g_conv + (long long)e*BHLc + (long long)b*Hc*Lc + l0;
    for (int i = tid; i < 1024; i += 64){
        int row = i >> 2, f4 = i & 3;
        *(float4*)&ygs[row*16 + f4*4] = *(const float4*)(src + (long long)row*Lc + f4*4);
    }
    __syncthreads();
    u64 aA[4][8], aG[4][8];
    #pragma unroll
    for (int r = 0; r < 4; ++r)
        #pragma unroll
        for (int k = 0; k < 8; ++k){ aA[r][k] = 0ull; aG[r][k] = 0ull; }
    const float2* wp = (const float2*)(g_woutT + lj*131072);
    float2 w0[4], w1[4];
    #pragma unroll
    for (int r = 0; r < 4; ++r){ w0[r] = wp[tid + r*64]; w1[r] = wp[256 + tid + r*64]; }
    for (int hp = 0; hp < 256; ++hp){
        int h2 = (hp < 254) ? hp + 2 : 255;
        float2 wf[4];
        #pragma unroll
        for (int r = 0; r < 4; ++r) wf[r] = wp[h2*256 + tid + r*64];
        const ulonglong2* yp = (const ulonglong2*)(ygs + hp*16);
        ulonglong2 ya = yp[0], yb = yp[1], yc = yp[2], yd = yp[3];
        #pragma unroll
        for (int r = 0; r < 4; ++r){
            u64 wa = pack2(w0[r].x), wg = pack2(w0[r].y);
            aA[r][0] = fma2(wa, ya.x, aA[r][0]); aG[r][0] = fma2(wg, ya.x, aG[r][0]);
            aA[r][1] = fma2(wa, ya.y, aA[r][1]); aG[r][1] = fma2(wg, ya.y, aG[r][1]);
            aA[r][2] = fma2(wa, yb.x, aA[r][2]); aG[r][2] = fma2(wg, yb.x, aG[r][2]);
            aA[r][3] = fma2(wa, yb.y, aA[r][3]); aG[r][3] = fma2(wg, yb.y, aG[r][3]);
            aA[r][4] = fma2(wa, yc.x, aA[r][4]); aG[r][4] = fma2(wg, yc.x, aG[r][4]);
            aA[r][5] = fma2(wa, yc.y, aA[r][5]); aG[r][5] = fma2(wg, yc.y, aG[r][5]);
            aA[r][6] = fma2(wa, yd.x, aA[r][6]); aG[r][6] = fma2(wg, yd.x, aG[r][6]);
            aA[r][7] = fma2(wa, yd.y, aA[r][7]); aG[r][7] = fma2(wg, yd.y, aG[r][7]);
        }
        #pragma unroll
        for (int r = 0; r < 4; ++r){ w0[r] = w1[r]; w1[r] = wf[r]; }
    }
    #pragma unroll
    for (int r = 0; r < 4; ++r){
        int h = tid + r*64;
        float ba = bout[lj*512 + h], bg = bout[lj*512 + 256 + h];
        float* dst = g_glu + (long long)e*BHLc + ((long long)(b*Hc + h))*Lc + l0;
        #pragma unroll
        for (int j = 0; j < 4; ++j){
            float2 a0 = upk(aA[r][2*j]), a1 = upk(aA[r][2*j+1]);
            float2 g0 = upk(aG[r][2*j]), g1 = upk(aG[r][2*j+1]);
            float4 ov;
            ov.x = (a0.x + ba) / (1.0f + expf(-(g0.x + bg)));
            ov.y = (a0.y + ba) / (1.0f + expf(-(g0.y + bg)));
            ov.z = (a1.x + ba) / (1.0f + expf(-(g1.x + bg)));
            ov.w = (a1.y + ba) / (1.0f + expf(-(g1.y + bg)));
            *(float4*)(dst + 4*j) = ov;
        }
    }
}

// ---------- combine: residual + LayerNorm over H ----------
__global__ __launch_bounds__(256) void k_combine(int layer, const float* __restrict__ gam,
                                                 const float* __restrict__ bet){
    __shared__ float s0[256*9];
    __shared__ float s1[256*9];
    __shared__ float red[4][8][8];
    int b = blockIdx.x >> 9, l0 = (blockIdx.x & 511) << 3, tid = threadIdx.x;
    for (int i = tid; i < 2048; i += 256){
        int h = i >> 3, t = i & 7;
        int idx = (b*Hc + h)*Lc + l0 + t;
        s0[h*9 + t] = g_xr[idx] + g_glu[idx] - g_glu[BHLc + idx];
        s1[h*9 + t] = g_xi[idx] + g_glu[2*BHLc + idx] + g_glu[3*BHLc + idx];
    }
    __syncthreads();
    int warp = tid >> 5, lane = tid & 31;
    float vr[8], vi[8];
    #pragma unroll
    for (int t = 0; t < 8; ++t){ vr[t] = s0[tid*9 + t]; vi[t] = s1[tid*9 + t]; }
    #pragma unroll
    for (int t = 0; t < 8; ++t){
        float a = vr[t], a2 = vr[t]*vr[t], c = vi[t], c2 = vi[t]*vi[t];
        #pragma unroll
        for (int o = 16; o; o >>= 1){
            a  += __shfl_xor_sync(0xffffffffu, a, o);
            a2 += __shfl_xor_sync(0xffffffffu, a2, o);
            c  += __shfl_xor_sync(0xffffffffu, c, o);
            c2 += __shfl_xor_sync(0xffffffffu, c2, o);
        }
        if (lane == 0){ red[0][t][warp] = a; red[1][t][warp] = a2; red[2][t][warp] = c; red[3][t][warp] = c2; }
    }
    __syncthreads();
    float gr = gam[(layer*2)*256 + tid],   brr = bet[(layer*2)*256 + tid];
    float gi = gam[(layer*2+1)*256 + tid], bii = bet[(layer*2+1)*256 + tid];
    float outr[8], outi[8];
    #pragma unroll
    for (int t = 0; t < 8; ++t){
        float sR = 0, qR = 0, sI = 0, qI = 0;
        #pragma unroll
        for (int w = 0; w < 8; ++w){ sR += red[0][t][w]; qR += red[1][t][w]; sI += red[2][t][w]; qI += red[3][t][w]; }
        float mR = sR*(1.0f/256), vR = qR*(1.0f/256) - mR*mR;
        float mI = sI*(1.0f/256), vI = qI*(1.0f/256) - mI*mI;
        float rR = rsqrtf(vR + 1e-5f), rI = rsqrtf(vI + 1e-5f);
        outr[t] = (vr[t] - mR)*rR*gr + brr;
        outi[t] = (vi[t] - mI)*rI*gi + bii;
    }
    int base = (b*Hc + tid)*Lc + l0;
    ((float4*)&g_xr[base])[0] = make_float4(outr[0], outr[1], outr[2], outr[3]);
    ((float4*)&g_xr[base])[1] = make_float4(outr[4], outr[5], outr[6], outr[7]);
    ((float4*)&g_xi[base])[0] = make_float4(outi[0], outi[1], outi[2], outi[3]);
    ((float4*)&g_xi[base])[1] = make_float4(outi[4], outi[5], outi[6], outi[7]);
}

// ---------- decoder main (o = 0..255) ----------
__global__ __launch_bounds__(256) void k_decoder(const float* __restrict__ br,
                                                 const float* __restrict__ bi, float* __restrict__ out){
    __shared__ __align__(16) float xsr[256*16];
    __shared__ __align__(16) float xsi[256*16];
    int b = blockIdx.x >> 8, l0 = (blockIdx.x & 255) << 4, tid = threadIdx.x;
    for (int i = tid; i < 4096; i += 256){
        int h = i >> 4, t = i & 15;
        int idx = (b*Hc + h)*Lc + l0 + t;
        xsr[i] = g_xr[idx]; xsi[i] = g_xi[idx];
    }
    __syncthreads();
    int o = tid;
    u64 pr[8], pi[8];
    #pragma unroll
    for (int p = 0; p < 8; ++p){ pr[p] = 0ull; pi[p] = 0ull; }
    for (int h = 0; h < 256; ++h){
        u64 wr2 = pack2(g_decT[0][h*DOUTc + o]);
        float wif = g_decT[1][h*DOUTc + o];
        u64 wi2 = pack2(wif), nwi2 = pack2(-wif);
        const ulonglong2* xr4 = (const ulonglong2*)&xsr[h*16];
        const ulonglong2* xi4 = (const ulonglong2*)&xsi[h*16];
        #pragma unroll
        for (int jq = 0; jq < 4; ++jq){
            ulonglong2 xr = xr4[jq], xi = xi4[jq];
            pr[2*jq]   = fma2(wr2, xr.x, pr[2*jq]);   pr[2*jq]   = fma2(nwi2, xi.x, pr[2*jq]);
            pi[2*jq]   = fma2(wi2, xr.x, pi[2*jq]);   pi[2*jq]   = fma2(wr2,  xi.x, pi[2*jq]);
            pr[2*jq+1] = fma2(wr2, xr.y, pr[2*jq+1]); pr[2*jq+1] = fma2(nwi2, xi.y, pr[2*jq+1]);
            pi[2*jq+1] = fma2(wi2, xr.y, pi[2*jq+1]); pi[2*jq+1] = fma2(wr2,  xi.y, pi[2*jq+1]);
        }
    }
    float brv = br[o], biv = bi[o];
    #pragma unroll
    for (int p = 0; p < 8; ++p){
        float2 a = upk(pr[p]), c = upk(pi[p]);
        long long t0 = (long long)(b*Lc + l0 + 2*p)*DOUTc + o;
        ((float2*)out)[t0] = make_float2(a.x + brv, c.x + biv);
        ((float2*)out)[t0 + DOUTc] = make_float2(a.y + brv, c.y + biv);
    }
}

// ---------- decoder tail column o = 256 ----------
__global__ __launch_bounds__(256) void k_dec256(const float* __restrict__ br,
                                                const float* __restrict__ bi, float* __restrict__ out){
    __shared__ float wr[256], wi[256];
    int tid = threadIdx.x;
    wr[tid] = g_decT[0][tid*DOUTc + 256];
    wi[tid] = g_decT[1][tid*DOUTc + 256];
    __syncthreads();
    int t = blockIdx.x*256 + tid;
    int b = t >> 12, l = t & 4095;
    float pr = 0.f, pi = 0.f;
    const float* xr = g_xr + b*Hc*Lc + l;
    const float* xi = g_xi + b*Hc*Lc + l;
    for (int h = 0; h < 256; ++h){
        float xrv = xr[h*Lc], xiv = xi[h*Lc];
        pr = fmaf(xrv, wr[h], pr); pr = fmaf(-xiv, wi[h], pr);
        pi = fmaf(xrv, wi[h], pi); pi = fmaf(xiv, wr[h], pi);
    }
    long long o0 = ((long long)(b*Lc + l)*DOUTc + 256);
    ((float2*)out)[o0] = make_float2(pr + br[256], pi + bi[256]);
}

extern "C" void kernel_launch(void* const* d_in, const int* in_sizes, int n_in,
                              void* d_out, int out_size){
    const float* x    = (const float*)d_in[0];
    const float* eWr  = (const float*)d_in[1];
    const float* eWi  = (const float*)d_in[2];
    const float* ebr  = (const float*)d_in[3];
    const float* ebi  = (const float*)d_in[4];
    const float* ldt  = (const float*)d_in[5];
    const float* lAr  = (const float*)d_in[6];
    const float* Aim  = (const float*)d_in[7];
    const float* C2   = (const float*)d_in[8];
    const float* s4D  = (const float*)d_in[9];
    const float* Wout = (const float*)d_in[10];
    const float* bout = (const float*)d_in[11];
    const float* gam  = (const float*)d_in[12];
    const float* bet  = (const float*)d_in[13];
    const float* dWr  = (const float*)d_in[14];
    const float* dWi  = (const float*)d_in[15];
    const float* dbr  = (const float*)d_in[16];
    const float* dbi  = (const float*)d_in[17];
    float* out = (float*)d_out;

    k_setup<<<512, 256>>>(eWr, eWi, dWr, dWi, Wout, ldt, lAr, Aim, C2);
    k_encoder<<<4096, 256>>>(x, ebr, ebi);
    for (int l = 0; l < NLc; ++l){
        k_scan<<<512, 128>>>(l, s4D);
        k_gemm<<<16384, 64>>>(l, bout);
        k_combine<<<8192, 256>>>(l, gam, bet);
    }
    k_decoder<<<4096, 256>>>(dbr, dbi, out);
    k_dec256<<<256, 256>>>(dbr, dbi, out);
}

// round 16
// speedup vs baseline: 1.2708x; 1.2708x over previous
#include <cuda_runtime.h>
#include <math.h>

#define Bc 16
#define Lc 4096
#define Hc 256
#define DINc 257
#define DOUTc 257
#define NLc 4
#define BHLc (Bc*Hc*Lc)

__device__ float  g_xr[BHLc];
__device__ float  g_xi[BHLc];
__device__ float  g_conv[4*BHLc];
__device__ float  g_glu[4*BHLc];
__device__ float  g_encT[2][DINc*Hc];
__device__ float  g_decT[2][Hc*DOUTc];
__device__ float  g_woutT[8*131072];   // [lj][hp][h][{a,g}] pairs
__device__ float4 g_coef[NLc*2*Hc*32];

typedef unsigned long long u64;

__device__ __forceinline__ u64 pack2(float v){ u64 r; asm("mov.b64 %0, {%1, %1};" : "=l"(r) : "f"(v)); return r; }
__device__ __forceinline__ u64 pk(float a, float b){ u64 r; asm("mov.b64 %0, {%1, %2};" : "=l"(r) : "f"(a), "f"(b)); return r; }
__device__ __forceinline__ u64 fma2(u64 a, u64 b, u64 c){ u64 d; asm("fma.rn.f32x2 %0, %1, %2, %3;" : "=l"(d) : "l"(a), "l"(b), "l"(c)); return d; }
__device__ __forceinline__ u64 mul2(u64 a, u64 b){ u64 d; asm("mul.rn.f32x2 %0, %1, %2;" : "=l"(d) : "l"(a), "l"(b)); return d; }
__device__ __forceinline__ float2 upk(u64 v){ float2 r; asm("mov.b64 {%0, %1}, %2;" : "=f"(r.x), "=f"(r.y) : "l"(v)); return r; }

// ---------- setup part 1: weight transposes ----------
__global__ void k_setup1(const float* __restrict__ eWr, const float* __restrict__ eWi,
                         const float* __restrict__ dWr, const float* __restrict__ dWi,
                         const float* __restrict__ Wout){
    int t0 = blockIdx.x*blockDim.x + threadIdx.x;
    int NT = gridDim.x*blockDim.x;
    for (int i = t0; i < DINc*Hc; i += NT){
        int d = i >> 8, h = i & 255;
        g_encT[0][i] = eWr[h*DINc + d];
        g_encT[1][i] = eWi[h*DINc + d];
    }
    for (int i = t0; i < Hc*DOUTc; i += NT){
        int h = i / DOUTc, o = i % DOUTc;
        g_decT[0][i] = dWr[o*Hc + h];
        g_decT[1][i] = dWi[o*Hc + h];
    }
    for (int i = t0; i < 8*131072; i += NT){
        int lj = i >> 17, r = i & 131071;
        int hp = r >> 9, h = (r >> 1) & 255, ag = r & 1;
        g_woutT[i] = Wout[lj*131072 + (ag*256 + h)*256 + hp];
    }
}
// ---------- setup part 2: SSM coefficients ----------
__global__ void k_setup2(const float* __restrict__ ldt, const float* __restrict__ lAr,
                         const float* __restrict__ Aim, const float* __restrict__ C2){
    int t = blockIdx.x*blockDim.x + threadIdx.x;
    if (t >= NLc*2*Hc*32) return;
    int h = (t >> 5) & 255, lj = t >> 13;
    double dt = exp((double)ldt[lj*256 + h]);
    double Ar = -exp((double)lAr[t]);
    double Ai = (double)Aim[t];
    double er = exp(dt*Ar);
    double wr = er*cos(dt*Ai), wi = er*sin(dt*Ai);
    double den = Ar*Ar + Ai*Ai;
    double Fr = ((wr-1.0)*Ar + wi*Ai)/den;
    double Fi = (wi*Ar - (wr-1.0)*Ai)/den;
    double Cr = (double)C2[t*2], Ci = (double)C2[t*2+1];
    g_coef[t] = make_float4((float)wr, (float)wi,
                            (float)(2.0*(Cr*Fr - Ci*Fi)), (float)(-2.0*(Cr*Fi + Ci*Fr)));
}

// ---------- encoder ----------
__global__ __launch_bounds__(256) void k_encoder(const float* __restrict__ x,
                                                 const float* __restrict__ br, const float* __restrict__ bi){
    __shared__ __align__(16) float xsr[DINc*16];
    __shared__ __align__(16) float xsi[DINc*16];
    int b = blockIdx.x >> 8, l0 = (blockIdx.x & 255) << 4, tid = threadIdx.x;
    const float* xb = x + ((long long)(b*Lc + l0))*DINc*2;
    for (int i = tid; i < 16*DINc*2; i += 256){
        int t = i / (DINc*2), dd = i % (DINc*2);
        float v = xb[i];
        if (dd & 1) xsi[(dd>>1)*16 + t] = v; else xsr[(dd>>1)*16 + t] = v;
    }
    __syncthreads();
    int h = tid;
    u64 yr[8], yi[8];
    #pragma unroll
    for (int p = 0; p < 8; ++p){ yr[p] = 0ull; yi[p] = 0ull; }
    for (int d = 0; d < DINc; ++d){
        u64 wr2 = pack2(g_encT[0][d*256 + h]);
        float wif = g_encT[1][d*256 + h];
        u64 wi2 = pack2(wif), nwi2 = pack2(-wif);
        const ulonglong2* xr4 = (const ulonglong2*)&xsr[d*16];
        const ulonglong2* xi4 = (const ulonglong2*)&xsi[d*16];
        #pragma unroll
        for (int j = 0; j < 4; ++j){
            ulonglong2 xr = xr4[j], xi = xi4[j];
            yr[2*j]   = fma2(wr2, xr.x, yr[2*j]);   yr[2*j]   = fma2(nwi2, xi.x, yr[2*j]);
            yi[2*j]   = fma2(wi2, xr.x, yi[2*j]);   yi[2*j]   = fma2(wr2,  xi.x, yi[2*j]);
            yr[2*j+1] = fma2(wr2, xr.y, yr[2*j+1]); yr[2*j+1] = fma2(nwi2, xi.y, yr[2*j+1]);
            yi[2*j+1] = fma2(wi2, xr.y, yi[2*j+1]); yi[2*j+1] = fma2(wr2,  xi.y, yi[2*j+1]);
        }
    }
    float brv = br[h], biv = bi[h];
    float2* pr = (float2*)&g_xr[(b*Hc + h)*Lc + l0];
    float2* pi = (float2*)&g_xi[(b*Hc + h)*Lc + l0];
    #pragma unroll
    for (int p = 0; p < 8; ++p){
        float2 a = upk(yr[p]), c = upk(yi[p]);
        pr[p] = make_float2(a.x + brv, a.y + brv);
        pi[p] = make_float2(c.x + biv, c.y + biv);
    }
}

// ---------- scan: 4 threads/(b,h), u prefetch, dual reduction accumulators ----------
__global__ __launch_bounds__(128) void k_scan(int layer, const float* __restrict__ s4D){
    int e = blockIdx.x >> 7, bhb = blockIdx.x & 127, tid = threadIdx.x;
    int g = tid >> 2, q = tid & 3;
    int bh = bhb*32 + g, h = bh & 255, jb = e & 1;
    const float* u = ((e == 0 || e == 3) ? g_xr : g_xi) + bh*Lc;
    float* outp = g_conv + e*BHLc + bh*Lc;
    u64 wr2[4], wi2[4], nwi2[4], kr2[4], ki2[4], sr2[4], si2[4];
    int cbase = ((layer*2 + jb)*256 + h)*32 + q*8;
    #pragma unroll
    for (int m = 0; m < 4; ++m){
        float4 c0 = g_coef[cbase + 2*m];
        float4 c1 = g_coef[cbase + 2*m + 1];
        wr2[m] = pk(c0.x, c1.x); wi2[m] = pk(c0.y, c1.y); nwi2[m] = pk(-c0.y, -c1.y);
        kr2[m] = pk(c0.z, c1.z); ki2[m] = pk(c0.w, c1.w);
        sr2[m] = 0ull; si2[m] = 0ull;
    }
    float Dv = s4D[(layer*2 + jb)*256 + h];
    float4 uv = *(const float4*)(u);
    for (int l = 0; l < Lc; l += 4){
        float4 uvn = (l + 4 < Lc) ? *(const float4*)(u + l + 4) : uv;
        float us[4] = {uv.x, uv.y, uv.z, uv.w};
        float cc[4];
        #pragma unroll
        for (int s = 0; s < 4; ++s){
            u64 u2 = pack2(us[s]), c2a = 0ull, c2b = 0ull;
            #pragma unroll
            for (int m = 0; m < 4; ++m){
                u64 t0 = fma2(wr2[m], sr2[m], u2);
                t0 = fma2(nwi2[m], si2[m], t0);
                u64 t1 = mul2(wr2[m], si2[m]);
                t1 = fma2(wi2[m], sr2[m], t1);
                sr2[m] = t0; si2[m] = t1;
                if (m & 1){ c2b = fma2(kr2[m], t0, c2b); c2b = fma2(ki2[m], t1, c2b); }
                else      { c2a = fma2(kr2[m], t0, c2a); c2a = fma2(ki2[m], t1, c2a); }
            }
            float2 ca = upk(c2a), cb = upk(c2b);
            float c = (ca.x + ca.y) + (cb.x + cb.y);
            c += __shfl_xor_sync(0xffffffffu, c, 1);
            c += __shfl_xor_sync(0xffffffffu, c, 2);
            cc[s] = fmaf(Dv, us[s], c);
        }
        if (q == 0){
            float4 gv;
            gv.x = 0.5f*cc[0]*(1.0f + erff(cc[0]*0.70710678f));
            gv.y = 0.5f*cc[1]*(1.0f + erff(cc[1]*0.70710678f));
            gv.z = 0.5f*cc[2]*(1.0f + erff(cc[2]*0.70710678f));
            gv.w = 0.5f*cc[3]*(1.0f + erff(cc[3]*0.70710678f));
            *(float4*)(outp + l) = gv;
        }
        uv = uvn;
    }
}

// ---------- FFMA2 GEMM + in-thread GLU: 128 threads, 2 rows (h, h+128), R13 config ----------
__global__ void __launch_bounds__(128, 2) k_gemm(int layer, const float* __restrict__ bout){
    __shared__ __align__(16) float ygs[256*32];      // 32 KB
    int tid = threadIdx.x;
    int e = blockIdx.x >> 11, b = (blockIdx.x >> 7) & 15, l0 = (blockIdx.x & 127) << 5;
    int lj = layer*2 + (e & 1);
    const float* src = g_conv + (long long)e*BHLc + (long long)b*Hc*Lc + l0;
    for (int i = tid; i < 2048; i += 128){
        int row = i >> 3, f4 = i & 7;
        *(float4*)&ygs[row*32 + f4*4] = *(const float4*)(src + (long long)row*Lc + f4*4);
    }
    __syncthreads();
    u64 aA0[16], aG0[16], aA1[16], aG1[16];
    #pragma unroll
    for (int k = 0; k < 16; ++k){ aA0[k] = 0ull; aG0[k] = 0ull; aA1[k] = 0ull; aG1[k] = 0ull; }
    const float2* wp = (const float2*)(g_woutT + lj*131072);
    float2 wA = wp[tid], wB = wp[tid + 128];
    float2 wC = wp[256 + tid], wD = wp[256 + tid + 128];
    const ulonglong2* yp = (const ulonglong2*)ygs;
    for (int hp = 0; hp < 256; hp += 2){
        int h2 = (hp < 254) ? hp + 2 : 254;
        int h3 = (hp < 253) ? hp + 3 : 254;
        float2 wnA = wp[h2*256 + tid], wnB = wp[h2*256 + tid + 128];
        float2 wnC = wp[h3*256 + tid], wnD = wp[h3*256 + tid + 128];
        u64 wa0 = pack2(wA.x), wg0 = pack2(wA.y);
        u64 wa1 = pack2(wB.x), wg1 = pack2(wB.y);
        #pragma unroll
        for (int j = 0; j < 8; ++j){
            ulonglong2 y = yp[j];
            aA0[2*j]   = fma2(wa0, y.x, aA0[2*j]);
            aG0[2*j]   = fma2(wg0, y.x, aG0[2*j]);
            aA1[2*j]   = fma2(wa1, y.x, aA1[2*j]);
            aG1[2*j]   = fma2(wg1, y.x, aG1[2*j]);
            aA0[2*j+1] = fma2(wa0, y.y, aA0[2*j+1]);
            aG0[2*j+1] = fma2(wg0, y.y, aG0[2*j+1]);
            aA1[2*j+1] = fma2(wa1, y.y, aA1[2*j+1]);
            aG1[2*j+1] = fma2(wg1, y.y, aG1[2*j+1]);
        }
        u64 wa2 = pack2(wC.x), wg2 = pack2(wC.y);
        u64 wa3 = pack2(wD.x), wg3 = pack2(wD.y);
        #pragma unroll
        for (int j = 0; j < 8; ++j){
            ulonglong2 y = yp[8+j];
            aA0[2*j]   = fma2(wa2, y.x, aA0[2*j]);
            aG0[2*j]   = fma2(wg2, y.x, aG0[2*j]);
            aA1[2*j]   = fma2(wa3, y.x, aA1[2*j]);
            aG1[2*j]   = fma2(wg3, y.x, aG1[2*j]);
            aA0[2*j+1] = fma2(wa2, y.y, aA0[2*j+1]);
            aG0[2*j+1] = fma2(wg2, y.y, aG0[2*j+1]);
            aA1[2*j+1] = fma2(wa3, y.y, aA1[2*j+1]);
            aG1[2*j+1] = fma2(wg3, y.y, aG1[2*j+1]);
        }
        yp += 16;
        wA = wnA; wB = wnB; wC = wnC; wD = wnD;
    }
    float ba0 = bout[lj*512 + tid],       bg0 = bout[lj*512 + 256 + tid];
    float ba1 = bout[lj*512 + tid + 128], bg1 = bout[lj*512 + 256 + tid + 128];
    float* dst0 = g_glu + (long long)e*BHLc + ((long long)(b*Hc + tid))*Lc + l0;
    float* dst1 = g_glu + (long long)e*BHLc + ((long long)(b*Hc + tid + 128))*Lc + l0;
    #pragma unroll
    for (int j = 0; j < 8; ++j){
        float2 a0 = upk(aA0[2*j]), a1 = upk(aA0[2*j+1]);
        float2 g0 = upk(aG0[2*j]), g1 = upk(aG0[2*j+1]);
        float4 ov;
        ov.x = (a0.x + ba0) / (1.0f + expf(-(g0.x + bg0)));
        ov.y = (a0.y + ba0) / (1.0f + expf(-(g0.y + bg0)));
        ov.z = (a1.x + ba0) / (1.0f + expf(-(g1.x + bg0)));
        ov.w = (a1.y + ba0) / (1.0f + expf(-(g1.y + bg0)));
        *(float4*)(dst0 + 4*j) = ov;
    }
    #pragma unroll
    for (int j = 0; j < 8; ++j){
        float2 a0 = upk(aA1[2*j]), a1 = upk(aA1[2*j+1]);
        float2 g0 = upk(aG1[2*j]), g1 = upk(aG1[2*j+1]);
        float4 ov;
        ov.x = (a0.x + ba1) / (1.0f + expf(-(g0.x + bg1)));
        ov.y = (a0.y + ba1) / (1.0f + expf(-(g0.y + bg1)));
        ov.z = (a1.x + ba1) / (1.0f + expf(-(g1.x + bg1)));
        ov.w = (a1.y + ba1) / (1.0f + expf(-(g1.y + bg1)));
        *(float4*)(dst1 + 4*j) = ov;
    }
}

// ---------- combine: residual + LayerNorm over H ----------
__global__ __launch_bounds__(256) void k_combine(int layer, const float* __restrict__ gam,
                                                 const float* __restrict__ bet){
    __shared__ float s0[256*9];
    __shared__ float s1[256*9];
    __shared__ float red[4][8][8];
    int b = blockIdx.x >> 9, l0 = (blockIdx.x & 511) << 3, tid = threadIdx.x;
    for (int i = tid; i < 2048; i += 256){
        int h = i >> 3, t = i & 7;
        int idx = (b*Hc + h)*Lc + l0 + t;
        s0[h*9 + t] = g_xr[idx] + g_glu[idx] - g_glu[BHLc + idx];
        s1[h*9 + t] = g_xi[idx] + g_glu[2*BHLc + idx] + g_glu[3*BHLc + idx];
    }
    __syncthreads();
    int warp = tid >> 5, lane = tid & 31;
    float vr[8], vi[8];
    #pragma unroll
    for (int t = 0; t < 8; ++t){ vr[t] = s0[tid*9 + t]; vi[t] = s1[tid*9 + t]; }
    #pragma unroll
    for (int t = 0; t < 8; ++t){
        float a = vr[t], a2 = vr[t]*vr[t], c = vi[t], c2 = vi[t]*vi[t];
        #pragma unroll
        for (int o = 16; o; o >>= 1){
            a  += __shfl_xor_sync(0xffffffffu, a, o);
            a2 += __shfl_xor_sync(0xffffffffu, a2, o);
            c  += __shfl_xor_sync(0xffffffffu, c, o);
            c2 += __shfl_xor_sync(0xffffffffu, c2, o);
        }
        if (lane == 0){ red[0][t][warp] = a; red[1][t][warp] = a2; red[2][t][warp] = c; red[3][t][warp] = c2; }
    }
    __syncthreads();
    float gr = gam[(layer*2)*256 + tid],   brr = bet[(layer*2)*256 + tid];
    float gi = gam[(layer*2+1)*256 + tid], bii = bet[(layer*2+1)*256 + tid];
    float outr[8], outi[8];
    #pragma unroll
    for (int t = 0; t < 8; ++t){
        float sR = 0, qR = 0, sI = 0, qI = 0;
        #pragma unroll
        for (int w = 0; w < 8; ++w){ sR += red[0][t][w]; qR += red[1][t][w]; sI += red[2][t][w]; qI += red[3][t][w]; }
        float mR = sR*(1.0f/256), vR = qR*(1.0f/256) - mR*mR;
        float mI = sI*(1.0f/256), vI = qI*(1.0f/256) - mI*mI;
        float rR = rsqrtf(vR + 1e-5f), rI = rsqrtf(vI + 1e-5f);
        outr[t] = (vr[t] - mR)*rR*gr + brr;
        outi[t] = (vi[t] - mI)*rI*gi + bii;
    }
    int base = (b*Hc + tid)*Lc + l0;
    ((float4*)&g_xr[base])[0] = make_float4(outr[0], outr[1], outr[2], outr[3]);
    ((float4*)&g_xr[base])[1] = make_float4(outr[4], outr[5], outr[6], outr[7]);
    ((float4*)&g_xi[base])[0] = make_float4(outi[0], outi[1], outi[2], outi[3]);
    ((float4*)&g_xi[base])[1] = make_float4(outi[4], outi[5], outi[6], outi[7]);
}

// ---------- decoder main (o = 0..255) ----------
__global__ __launch_bounds__(256) void k_decoder(const float* __restrict__ br,
                                                 const float* __restrict__ bi, float* __restrict__ out){
    __shared__ __align__(16) float xsr[256*16];
    __shared__ __align__(16) float xsi[256*16];
    int b = blockIdx.x >> 8, l0 = (blockIdx.x & 255) << 4, tid = threadIdx.x;
    for (int i = tid; i < 4096; i += 256){
        int h = i >> 4, t = i & 15;
        int idx = (b*Hc + h)*Lc + l0 + t;
        xsr[i] = g_xr[idx]; xsi[i] = g_xi[idx];
    }
    __syncthreads();
    int o = tid;
    u64 pr[8], pi[8];
    #pragma unroll
    for (int p = 0; p < 8; ++p){ pr[p] = 0ull; pi[p] = 0ull; }
    for (int h = 0; h < 256; ++h){
        u64 wr2 = pack2(g_decT[0][h*DOUTc + o]);
        float wif = g_decT[1][h*DOUTc + o];
        u64 wi2 = pack2(wif), nwi2 = pack2(-wif);
        const ulonglong2* xr4 = (const ulonglong2*)&xsr[h*16];
        const ulonglong2* xi4 = (const ulonglong2*)&xsi[h*16];
        #pragma unroll
        for (int jq = 0; jq < 4; ++jq){
            ulonglong2 xr = xr4[jq], xi = xi4[jq];
            pr[2*jq]   = fma2(wr2, xr.x, pr[2*jq]);   pr[2*jq]   = fma2(nwi2, xi.x, pr[2*jq]);
            pi[2*jq]   = fma2(wi2, xr.x, pi[2*jq]);   pi[2*jq]   = fma2(wr2,  xi.x, pi[2*jq]);
            pr[2*jq+1] = fma2(wr2, xr.y, pr[2*jq+1]); pr[2*jq+1] = fma2(nwi2, xi.y, pr[2*jq+1]);
            pi[2*jq+1] = fma2(wi2, xr.y, pi[2*jq+1]); pi[2*jq+1] = fma2(wr2,  xi.y, pi[2*jq+1]);
        }
    }
    float brv = br[o], biv = bi[o];
    #pragma unroll
    for (int p = 0; p < 8; ++p){
        float2 a = upk(pr[p]), c = upk(pi[p]);
        long long t0 = (long long)(b*Lc + l0 + 2*p)*DOUTc + o;
        ((float2*)out)[t0] = make_float2(a.x + brv, c.x + biv);
        ((float2*)out)[t0 + DOUTc] = make_float2(a.y + brv, c.y + biv);
    }
}

// ---------- decoder tail column o = 256 ----------
__global__ __launch_bounds__(256) void k_dec256(const float* __restrict__ br,
                                                const float* __restrict__ bi, float* __restrict__ out){
    __shared__ float wr[256], wi[256];
    int tid = threadIdx.x;
    wr[tid] = g_decT[0][tid*DOUTc + 256];
    wi[tid] = g_decT[1][tid*DOUTc + 256];
    __syncthreads();
    int t = blockIdx.x*256 + tid;
    int b = t >> 12, l = t & 4095;
    float pr = 0.f, pi = 0.f;
    const float* xr = g_xr + b*Hc*Lc + l;
    const float* xi = g_xi + b*Hc*Lc + l;
    for (int h = 0; h < 256; ++h){
        float xrv = xr[h*Lc], xiv = xi[h*Lc];
        pr = fmaf(xrv, wr[h], pr); pr = fmaf(-xiv, wi[h], pr);
        pi = fmaf(xrv, wi[h], pi); pi = fmaf(xiv, wr[h], pi);
    }
    long long o0 = ((long long)(b*Lc + l)*DOUTc + 256);
    ((float2*)out)[o0] = make_float2(pr + br[256], pi + bi[256]);
}

extern "C" void kernel_launch(void* const* d_in, const int* in_sizes, int n_in,
                              void* d_out, int out_size){
    const float* x    = (const float*)d_in[0];
    const float* eWr  = (const float*)d_in[1];
    const float* eWi  = (const float*)d_in[2];
    const float* ebr  = (const float*)d_in[3];
    const float* ebi  = (const float*)d_in[4];
    const float* ldt  = (const float*)d_in[5];
    const float* lAr  = (const float*)d_in[6];
    const float* Aim  = (const float*)d_in[7];
    const float* C2   = (const float*)d_in[8];
    const float* s4D  = (const float*)d_in[9];
    const float* Wout = (const float*)d_in[10];
    const float* bout = (const float*)d_in[11];
    const float* gam  = (const float*)d_in[12];
    const float* bet  = (const float*)d_in[13];
    const float* dWr  = (const float*)d_in[14];
    const float* dWi  = (const float*)d_in[15];
    const float* dbr  = (const float*)d_in[16];
    const float* dbi  = (const float*)d_in[17];
    float* out = (float*)d_out;

    k_setup1<<<512, 256>>>(eWr, eWi, dWr, dWi, Wout);
    k_setup2<<<256, 256>>>(ldt, lAr, Aim, C2);
    k_encoder<<<4096, 256>>>(x, ebr, ebi);
    for (int l = 0; l < NLc; ++l){
        k_scan<<<512, 128>>>(l, s4D);
        k_gemm<<<8192, 128>>>(l, bout);
        k_combine<<<8192, 256>>>(l, gam, bet);
    }
    k_decoder<<<4096, 256>>>(dbr, dbi, out);
    k_dec256<<<256, 256>>>(dbr, dbi, out);
}